// round 11
// baseline (speedup 1.0000x reference)
#include <cuda_runtime.h>
#include <cuda_bf16.h>
#include <cstdint>

// ===========================================================================
// InnerMonologue: single-pass TF32 GEMMs on mma.sync.m16n8k8.
// CTA tile 128x256, 8 warps of 64x64 (fragment reuse: 0.125 B/MAC), BK=32,
// 3-stage cp.async. Weights pre-transposed+tf32-rounded; A rounded post-ldsm.
// Output: [PR (BS*P)] [OUT (BS*H)] [is_private (BS)] [usage (B)]  (all fp32)
// ===========================================================================

#define MAX_S 32768
#define MAX_WE (2048 * 256)

__device__ unsigned char g_mask[MAX_S];
__device__ float g_Wt[MAX_WE];  // W_to  transposed [P][H], tf32-rounded
__device__ float g_Wf[MAX_WE];  // W_from transposed [H][P], tf32-rounded

__device__ __forceinline__ uint32_t smem_u32(const void* p) {
    uint32_t a;
    asm("{ .reg .u64 t; cvta.to.shared.u64 t, %1; cvt.u32.u64 %0, t; }"
        : "=r"(a) : "l"(p));
    return a;
}
__device__ __forceinline__ void ldsm_x4(uint32_t addr, uint32_t* r) {
    asm volatile("ldmatrix.sync.aligned.m8n8.x4.shared.b16 {%0,%1,%2,%3}, [%4];"
                 : "=r"(r[0]), "=r"(r[1]), "=r"(r[2]), "=r"(r[3])
                 : "r"(addr));
}
__device__ __forceinline__ uint32_t cvt_tf32(uint32_t x) {
    uint32_t o;
    float f = __uint_as_float(x);
    asm("cvt.rna.tf32.f32 %0, %1;" : "=r"(o) : "f"(f));
    return o;
}
__device__ __forceinline__ void mma_tf32(float* c, const uint32_t* a,
                                         const uint32_t* b) {
    asm volatile(
        "mma.sync.aligned.m16n8k8.row.col.f32.tf32.tf32.f32 "
        "{%0,%1,%2,%3}, {%4,%5,%6,%7}, {%8,%9}, {%0,%1,%2,%3};"
        : "+f"(c[0]), "+f"(c[1]), "+f"(c[2]), "+f"(c[3])
        : "r"(a[0]), "r"(a[1]), "r"(a[2]), "r"(a[3]), "r"(b[0]), "r"(b[1]));
}
__device__ __forceinline__ void cp16(uint32_t dst, const void* src) {
    asm volatile("cp.async.cg.shared.global [%0], [%1], 16;"
                 :: "r"(dst), "l"(src));
}
#define CP_COMMIT() asm volatile("cp.async.commit_group;" ::: "memory")
#define CP_WAIT1()  asm volatile("cp.async.wait_group 1;" ::: "memory")

// SMEM rows: 32 fp32 (128B) + 16B pad = 144B stride -> conflict-free ldsm.
#define ROWB 144
#define A_T (128 * ROWB)               // 18432
#define B_T (256 * ROWB)               // 36864
#define STAGE_B (A_T + B_T)            // 55296
#define ST_OFF(st) ((st) * STAGE_B)
#define SM_DYN (3 * STAGE_B)           // 165888

// ===========================================================================
// GEMM: C[128,256] = A[M,K]fp32 @ B[N,K]fp32(tf32)^T + bias (+mask blend).
// 256 threads, 8 warps (2x4), warp tile 64x64, BK=32, 3-stage cp.async.
// ===========================================================================
template <bool MASKED, bool USE_WF>
__global__ void __launch_bounds__(256, 1)
gemm_tf32(const float* __restrict__ A, const float* __restrict__ bias,
          const float* __restrict__ HS, float* __restrict__ OUT,
          int K, int Ntot, int S) {
    extern __shared__ __align__(16) char smem[];
    __shared__ unsigned char smask[128];
    __shared__ int s_cnt;

    const float* __restrict__ Bw = USE_WF ? g_Wf : g_Wt;

    const int tid = threadIdx.x;
    const int wid = tid >> 5;
    const int lane = tid & 31;
    const int m0 = blockIdx.y * 128;
    const int n0 = blockIdx.x * 256;

    if (MASKED) {
        if (tid == 0) s_cnt = 0;
        __syncthreads();
        if (tid < 128) {
            unsigned char mm = g_mask[(m0 + tid) % S];
            smask[tid] = mm;
            if (mm) atomicAdd(&s_cnt, 1);
        }
        __syncthreads();
        if (s_cnt == 0) {  // all-public tile: copy HS slab (128 x 256)
            const size_t base = (size_t)m0 * Ntot + n0;
            for (int i = tid; i < 128 * 64; i += 256) {
                int r = i >> 6, c = (i & 63) << 2;
                *(float4*)&OUT[base + (size_t)r * Ntot + c] =
                    *(const float4*)&HS[base + (size_t)r * Ntot + c];
            }
            return;
        }
    }

    const uint32_t sbase = smem_u32(smem);
    const int wm = (wid >> 2) * 64;  // 2 warp rows
    const int wn = (wid & 3) * 64;   // 4 warp cols

    // cp.async: A 1024 16B-units (4/thread), B 2048 (8/thread).
    auto cp_stage = [&](int s, int st) {
        const int k0 = s << 5;
        const uint32_t dA = sbase + ST_OFF(st);
        const uint32_t dB = dA + A_T;
#pragma unroll
        for (int i = 0; i < 4; i++) {
            int u = tid * 4 + i;
            int row = u >> 3, col = u & 7;
            cp16(dA + row * ROWB + col * 16,
                 A + (size_t)(m0 + row) * K + k0 + col * 4);
        }
#pragma unroll
        for (int i = 0; i < 8; i++) {
            int u = tid * 8 + i;
            int row = u >> 3, col = u & 7;
            cp16(dB + row * ROWB + col * 16,
                 Bw + (size_t)(n0 + row) * K + k0 + col * 4);
        }
    };

    float acc[4][8][4];
#pragma unroll
    for (int mt = 0; mt < 4; mt++)
#pragma unroll
        for (int nt = 0; nt < 8; nt++)
#pragma unroll
            for (int i = 0; i < 4; i++) acc[mt][nt][i] = 0.f;

    auto compute = [&](int st) {
        const uint32_t uA = sbase + ST_OFF(st);
        const uint32_t uB = uA + A_T;
        const int r8 = lane & 7;
        const int mat = lane >> 3;  // 0..3
#pragma unroll
        for (int kp = 0; kp < 4; kp++) {  // four k8 steps per BK=32
            const int kb = kp * 32;
            uint32_t af[4][4], bf[4][4];
#pragma unroll
            for (int mt = 0; mt < 4; mt++) {
                int arow = wm + mt * 16 + (mat & 1) * 8 + r8;
                uint32_t off = (uint32_t)(arow * ROWB + kb + (mat >> 1) * 16);
                ldsm_x4(uA + off, af[mt]);
#pragma unroll
                for (int i = 0; i < 4; i++) af[mt][i] = cvt_tf32(af[mt][i]);
            }
#pragma unroll
            for (int g = 0; g < 4; g++) {
                int brow = wn + g * 16 + (mat & 1) * 8 + r8;
                uint32_t off = (uint32_t)(brow * ROWB + kb + (mat >> 1) * 16);
                ldsm_x4(uB + off, bf[g]);
            }
#pragma unroll
            for (int g = 0; g < 4; g++) {
                uint32_t b0[2] = {bf[g][0], bf[g][2]};  // n 0-7
                uint32_t b1[2] = {bf[g][1], bf[g][3]};  // n 8-15
#pragma unroll
                for (int mt = 0; mt < 4; mt++) {
                    mma_tf32(acc[mt][2 * g], af[mt], b0);
                    mma_tf32(acc[mt][2 * g + 1], af[mt], b1);
                }
            }
        }
    };

    const int nk = K >> 5;
    cp_stage(0, 0); CP_COMMIT();
    cp_stage(1, 1); CP_COMMIT();
    int st = 0;
    for (int s = 0; s < nk; s++) {
        CP_WAIT1();
        __syncthreads();
        if (s + 2 < nk) {
            int st2 = st + 2; if (st2 >= 3) st2 -= 3;
            cp_stage(s + 2, st2);
            CP_COMMIT();
        }
        compute(st);
        if (++st == 3) st = 0;
    }

    // ---- Epilogue ----
    const int qr = lane >> 2;
    const int qc = (lane & 3) * 2;
#pragma unroll
    for (int mt = 0; mt < 4; mt++) {
        const int lr0 = wm + mt * 16 + qr;
        const int lr1 = lr0 + 8;
        const size_t rb0 = (size_t)(m0 + lr0) * Ntot;
        const size_t rb1 = (size_t)(m0 + lr1) * Ntot;
        const bool p0 = !MASKED || (smask[lr0] != 0);
        const bool p1 = !MASKED || (smask[lr1] != 0);
#pragma unroll
        for (int nt = 0; nt < 8; nt++) {
            const int col = n0 + wn + nt * 8 + qc;
            float2 b2 = *(const float2*)&bias[col];
            float2 v0, v1;
            v0.x = acc[mt][nt][0] + b2.x;
            v0.y = acc[mt][nt][1] + b2.y;
            v1.x = acc[mt][nt][2] + b2.x;
            v1.y = acc[mt][nt][3] + b2.y;
            if (MASKED) {
                if (!p0) v0 = *(const float2*)&HS[rb0 + col];
                if (!p1) v1 = *(const float2*)&HS[rb1 + col];
            }
            *(float2*)&OUT[rb0 + col] = v0;
            *(float2*)&OUT[rb1 + col] = v1;
        }
    }
}

// ===========================================================================
// Mask scan, broadcast, weight transpose (+tf32 pre-round) kernels.
// ===========================================================================
__global__ void scan_kernel(const int* __restrict__ tok,
                            const int* __restrict__ ttid_p,
                            float* __restrict__ usage_out, int B, int S) {
    __shared__ int stok[8192];
    __shared__ int sc[256];
    const int ttid = *ttid_p;
    const int tid = threadIdx.x;
    const bool fits = (S <= 8192);
    if (fits)
        for (int i = tid; i < S; i += 256) stok[i] = tok[i];
    __syncthreads();
    const int* src = fits ? stok : tok;

    const int chunk = (S + 255) / 256;
    const int start = tid * chunk;
    const int end = min(start + chunk, S);
    int cnt = 0;
    for (int i = start; i < end; i++) cnt += (src[i] == ttid);
    sc[tid] = cnt;
    __syncthreads();
    for (int off = 1; off < 256; off <<= 1) {
        int v = (tid >= off) ? sc[tid - off] : 0;
        __syncthreads();
        sc[tid] += v;
        __syncthreads();
    }
    int run = sc[tid] - cnt;
    int ones = 0;
    for (int i = start; i < end; i++) {
        run += (src[i] == ttid);
        unsigned char m = (unsigned char)(run & 1);
        g_mask[i] = m;
        ones += m;
    }
    __syncthreads();
    sc[tid] = ones;
    __syncthreads();
    for (int off = 128; off > 0; off >>= 1) {
        if (tid < off) sc[tid] += sc[tid + off];
        __syncthreads();
    }
    if (tid < B) usage_out[tid] = (float)sc[0] / (float)S;
}

__global__ void bcast_kernel(float* __restrict__ out_mask, int BS, int S) {
    int i = blockIdx.x * blockDim.x + threadIdx.x;
    if (i < BS) out_mask[i] = (float)g_mask[i % S];
}

__device__ __forceinline__ float round_tf32(float v) {
    uint32_t o;
    asm("cvt.rna.tf32.f32 %0, %1;" : "=r"(o) : "f"(v));
    return __uint_as_float(o);
}

__global__ void conv_w_kernel(const float* __restrict__ W_to,
                              const float* __restrict__ W_from, int H, int P) {
    int idx = blockIdx.x * blockDim.x + threadIdx.x;
    if (idx >= H * P) return;
    {  // W_to [H][P] -> Wt [P][H], tf32-rounded
        int k = idx / P, n = idx - k * P;
        g_Wt[n * H + k] = round_tf32(W_to[idx]);
    }
    {  // W_from [P][H] -> Wf [H][P], tf32-rounded
        int p = idx / H, hh = idx - p * H;
        g_Wf[hh * P + p] = round_tf32(W_from[idx]);
    }
}

// ===========================================================================
extern "C" void kernel_launch(void* const* d_in, const int* in_sizes, int n_in,
                              void* d_out, int out_size) {
    const float* hidden = (const float*)d_in[0];
    const float* W_to   = (const float*)d_in[1];
    const float* b_to   = (const float*)d_in[2];
    const float* W_from = (const float*)d_in[3];
    const float* b_from = (const float*)d_in[4];
    const int*   token  = (const int*)d_in[5];
    const int*   ttid   = (const int*)d_in[6];

    const int P  = in_sizes[2];
    const int H  = in_sizes[4];
    const int BS = in_sizes[5];
    const int B  = out_size - BS * (P + H + 1);
    const int S  = BS / B;

    float* out = (float*)d_out;
    float* out_pr    = out;
    float* out_o     = out + (size_t)BS * P;
    float* out_mask  = out_o + (size_t)BS * H;
    float* out_usage = out_mask + BS;

    cudaFuncSetAttribute(gemm_tf32<false, false>,
                         cudaFuncAttributeMaxDynamicSharedMemorySize, SM_DYN);
    cudaFuncSetAttribute(gemm_tf32<true, true>,
                         cudaFuncAttributeMaxDynamicSharedMemorySize, SM_DYN);

    scan_kernel<<<1, 256>>>(token, ttid, out_usage, B, S);
    bcast_kernel<<<(BS + 255) / 256, 256>>>(out_mask, BS, S);
    conv_w_kernel<<<(H * P + 255) / 256, 256>>>(W_to, W_from, H, P);

    // GEMM1: PR = HS @ W_to + b_to   (M=BS, N=P=256, K=H)
    gemm_tf32<false, false><<<dim3(P / 256, BS / 128), 256, SM_DYN>>>(
        hidden, b_to, nullptr, out_pr, H, P, S);

    // GEMM2: OUT = blend(PR @ W_from + b_from, HS)  (M=BS, N=H, K=P)
    gemm_tf32<true, true><<<dim3(H / 256, BS / 128), 256, SM_DYN>>>(
        out_pr, b_from, hidden, out_o, P, H, S);
}

// round 12
// speedup vs baseline: 1.0761x; 1.0761x over previous
#include <cuda_runtime.h>
#include <cuda_bf16.h>
#include <cstdint>

// ===========================================================================
// InnerMonologue: single-pass TF32 GEMMs on mma.sync.m16n8k8.
// CTA 128x128, 256 threads (8 warps, warp tile 32x64), BK=32, 3-stage
// cp.async, 108KB smem + <=128 regs -> 2 CTAs/SM (16 warps, decorrelated
// barriers). Weights pre-transposed + tf32-rounded; A rounded post-ldsm.
// Output: [PR (BS*P)] [OUT (BS*H)] [is_private (BS)] [usage (B)]  (all fp32)
// ===========================================================================

#define MAX_S 32768
#define MAX_WE (2048 * 256)

__device__ unsigned char g_mask[MAX_S];
__device__ float g_Wt[MAX_WE];  // W_to  transposed [P][H], tf32-rounded
__device__ float g_Wf[MAX_WE];  // W_from transposed [H][P], tf32-rounded

__device__ __forceinline__ uint32_t smem_u32(const void* p) {
    uint32_t a;
    asm("{ .reg .u64 t; cvta.to.shared.u64 t, %1; cvt.u32.u64 %0, t; }"
        : "=r"(a) : "l"(p));
    return a;
}
__device__ __forceinline__ void ldsm_x4(uint32_t addr, uint32_t* r) {
    asm volatile("ldmatrix.sync.aligned.m8n8.x4.shared.b16 {%0,%1,%2,%3}, [%4];"
                 : "=r"(r[0]), "=r"(r[1]), "=r"(r[2]), "=r"(r[3])
                 : "r"(addr));
}
__device__ __forceinline__ uint32_t cvt_tf32(uint32_t x) {
    uint32_t o;
    float f = __uint_as_float(x);
    asm("cvt.rna.tf32.f32 %0, %1;" : "=r"(o) : "f"(f));
    return o;
}
__device__ __forceinline__ void mma_tf32(float* c, const uint32_t* a,
                                         const uint32_t* b) {
    asm volatile(
        "mma.sync.aligned.m16n8k8.row.col.f32.tf32.tf32.f32 "
        "{%0,%1,%2,%3}, {%4,%5,%6,%7}, {%8,%9}, {%0,%1,%2,%3};"
        : "+f"(c[0]), "+f"(c[1]), "+f"(c[2]), "+f"(c[3])
        : "r"(a[0]), "r"(a[1]), "r"(a[2]), "r"(a[3]), "r"(b[0]), "r"(b[1]));
}
__device__ __forceinline__ void cp16(uint32_t dst, const void* src) {
    asm volatile("cp.async.cg.shared.global [%0], [%1], 16;"
                 :: "r"(dst), "l"(src));
}
#define CP_COMMIT() asm volatile("cp.async.commit_group;" ::: "memory")
#define CP_WAIT1()  asm volatile("cp.async.wait_group 1;" ::: "memory")

// SMEM rows: 32 fp32 (128B) + 16B pad = 144B stride -> conflict-free ldsm.
#define ROWB 144
#define TILE_B (128 * ROWB)            // 18432
#define STAGE_B (2 * TILE_B)           // 36864
#define ST_OFF(st) ((st) * STAGE_B)
#define SM_DYN (3 * STAGE_B)           // 110592 (108KB) -> 2 CTAs/SM

// ===========================================================================
// GEMM: C[128,128] = A[M,K]fp32 @ B[N,K]fp32(tf32)^T + bias (+mask blend).
// 256 threads, 8 warps (4M x 2N), warp tile 32x64, BK=32, 3-stage cp.async.
// ===========================================================================
template <bool MASKED, bool USE_WF>
__global__ void __launch_bounds__(256, 2)
gemm_tf32(const float* __restrict__ A, const float* __restrict__ bias,
          const float* __restrict__ HS, float* __restrict__ OUT,
          int K, int Ntot, int S) {
    extern __shared__ __align__(16) char smem[];
    __shared__ unsigned char smask[128];
    __shared__ int s_cnt;

    const float* __restrict__ Bw = USE_WF ? g_Wf : g_Wt;

    const int tid = threadIdx.x;
    const int wid = tid >> 5;
    const int lane = tid & 31;
    const int m0 = blockIdx.y * 128;
    const int n0 = blockIdx.x * 128;

    if (MASKED) {
        if (tid == 0) s_cnt = 0;
        __syncthreads();
        if (tid < 128) {
            unsigned char mm = g_mask[(m0 + tid) % S];
            smask[tid] = mm;
            if (mm) atomicAdd(&s_cnt, 1);
        }
        __syncthreads();
        if (s_cnt == 0) {  // all-public tile: straight copy of HS slab
            const size_t base = (size_t)m0 * Ntot + n0;
            for (int i = tid; i < 128 * 32; i += 256) {
                int r = i >> 5, c = (i & 31) << 2;
                *(float4*)&OUT[base + (size_t)r * Ntot + c] =
                    *(const float4*)&HS[base + (size_t)r * Ntot + c];
            }
            return;
        }
    }

    const uint32_t sbase = smem_u32(smem);
    const int wm = (wid >> 1) * 32;  // 4 warp rows
    const int wn = (wid & 1) * 64;   // 2 warp cols

    // cp.async: A 1024 16B-units (4/thread), B 1024 (4/thread).
    auto cp_stage = [&](int s, int st) {
        const int k0 = s << 5;
        const uint32_t dA = sbase + ST_OFF(st);
        const uint32_t dB = dA + TILE_B;
#pragma unroll
        for (int i = 0; i < 4; i++) {
            int u = tid * 4 + i;
            int row = u >> 3, col = u & 7;
            uint32_t doff = row * ROWB + col * 16;
            cp16(dA + doff, A + (size_t)(m0 + row) * K + k0 + col * 4);
            cp16(dB + doff, Bw + (size_t)(n0 + row) * K + k0 + col * 4);
        }
    };

    float acc[2][8][4];
#pragma unroll
    for (int mt = 0; mt < 2; mt++)
#pragma unroll
        for (int nt = 0; nt < 8; nt++)
#pragma unroll
            for (int i = 0; i < 4; i++) acc[mt][nt][i] = 0.f;

    auto compute = [&](int st) {
        const uint32_t uA = sbase + ST_OFF(st);
        const uint32_t uB = uA + TILE_B;
        const int r8 = lane & 7;
        const int mat = lane >> 3;  // 0..3
#pragma unroll
        for (int kp = 0; kp < 4; kp++) {  // four k8 steps per BK=32
            const int kb = kp * 32;
            uint32_t af[2][4];
#pragma unroll
            for (int mt = 0; mt < 2; mt++) {
                int arow = wm + mt * 16 + (mat & 1) * 8 + r8;
                uint32_t off = (uint32_t)(arow * ROWB + kb + (mat >> 1) * 16);
                ldsm_x4(uA + off, af[mt]);
#pragma unroll
                for (int i = 0; i < 4; i++) af[mt][i] = cvt_tf32(af[mt][i]);
            }
#pragma unroll
            for (int g = 0; g < 4; g++) {
                int brow = wn + g * 16 + (mat & 1) * 8 + r8;
                uint32_t off = (uint32_t)(brow * ROWB + kb + (mat >> 1) * 16);
                uint32_t bf[4];
                ldsm_x4(uB + off, bf);
                uint32_t b0[2] = {bf[0], bf[2]};  // n 0-7
                uint32_t b1[2] = {bf[1], bf[3]};  // n 8-15
#pragma unroll
                for (int mt = 0; mt < 2; mt++) {
                    mma_tf32(acc[mt][2 * g], af[mt], b0);
                    mma_tf32(acc[mt][2 * g + 1], af[mt], b1);
                }
            }
        }
    };

    const int nk = K >> 5;
    cp_stage(0, 0); CP_COMMIT();
    cp_stage(1, 1); CP_COMMIT();
    int st = 0;
    for (int s = 0; s < nk; s++) {
        CP_WAIT1();
        __syncthreads();
        if (s + 2 < nk) {
            int st2 = st + 2; if (st2 >= 3) st2 -= 3;
            cp_stage(s + 2, st2);
            CP_COMMIT();
        }
        compute(st);
        if (++st == 3) st = 0;
    }

    // ---- Epilogue ----
    const int qr = lane >> 2;
    const int qc = (lane & 3) * 2;
#pragma unroll
    for (int mt = 0; mt < 2; mt++) {
        const int lr0 = wm + mt * 16 + qr;
        const int lr1 = lr0 + 8;
        const size_t rb0 = (size_t)(m0 + lr0) * Ntot;
        const size_t rb1 = (size_t)(m0 + lr1) * Ntot;
        const bool p0 = !MASKED || (smask[lr0] != 0);
        const bool p1 = !MASKED || (smask[lr1] != 0);
#pragma unroll
        for (int nt = 0; nt < 8; nt++) {
            const int col = n0 + wn + nt * 8 + qc;
            float2 b2 = *(const float2*)&bias[col];
            float2 v0, v1;
            v0.x = acc[mt][nt][0] + b2.x;
            v0.y = acc[mt][nt][1] + b2.y;
            v1.x = acc[mt][nt][2] + b2.x;
            v1.y = acc[mt][nt][3] + b2.y;
            if (MASKED) {
                if (!p0) v0 = *(const float2*)&HS[rb0 + col];
                if (!p1) v1 = *(const float2*)&HS[rb1 + col];
            }
            *(float2*)&OUT[rb0 + col] = v0;
            *(float2*)&OUT[rb1 + col] = v1;
        }
    }
}

// ===========================================================================
// Mask scan, broadcast, weight transpose (+tf32 pre-round) kernels.
// ===========================================================================
__global__ void scan_kernel(const int* __restrict__ tok,
                            const int* __restrict__ ttid_p,
                            float* __restrict__ usage_out, int B, int S) {
    __shared__ int stok[8192];
    __shared__ int sc[256];
    const int ttid = *ttid_p;
    const int tid = threadIdx.x;
    const bool fits = (S <= 8192);
    if (fits)
        for (int i = tid; i < S; i += 256) stok[i] = tok[i];
    __syncthreads();
    const int* src = fits ? stok : tok;

    const int chunk = (S + 255) / 256;
    const int start = tid * chunk;
    const int end = min(start + chunk, S);
    int cnt = 0;
    for (int i = start; i < end; i++) cnt += (src[i] == ttid);
    sc[tid] = cnt;
    __syncthreads();
    for (int off = 1; off < 256; off <<= 1) {
        int v = (tid >= off) ? sc[tid - off] : 0;
        __syncthreads();
        sc[tid] += v;
        __syncthreads();
    }
    int run = sc[tid] - cnt;
    int ones = 0;
    for (int i = start; i < end; i++) {
        run += (src[i] == ttid);
        unsigned char m = (unsigned char)(run & 1);
        g_mask[i] = m;
        ones += m;
    }
    __syncthreads();
    sc[tid] = ones;
    __syncthreads();
    for (int off = 128; off > 0; off >>= 1) {
        if (tid < off) sc[tid] += sc[tid + off];
        __syncthreads();
    }
    if (tid < B) usage_out[tid] = (float)sc[0] / (float)S;
}

__global__ void bcast_kernel(float* __restrict__ out_mask, int BS, int S) {
    int i = blockIdx.x * blockDim.x + threadIdx.x;
    if (i < BS) out_mask[i] = (float)g_mask[i % S];
}

__device__ __forceinline__ float round_tf32(float v) {
    uint32_t o;
    asm("cvt.rna.tf32.f32 %0, %1;" : "=r"(o) : "f"(v));
    return __uint_as_float(o);
}

__global__ void conv_w_kernel(const float* __restrict__ W_to,
                              const float* __restrict__ W_from, int H, int P) {
    int idx = blockIdx.x * blockDim.x + threadIdx.x;
    if (idx >= H * P) return;
    {  // W_to [H][P] -> Wt [P][H], tf32-rounded
        int k = idx / P, n = idx - k * P;
        g_Wt[n * H + k] = round_tf32(W_to[idx]);
    }
    {  // W_from [P][H] -> Wf [H][P], tf32-rounded
        int p = idx / H, hh = idx - p * H;
        g_Wf[hh * P + p] = round_tf32(W_from[idx]);
    }
}

// ===========================================================================
extern "C" void kernel_launch(void* const* d_in, const int* in_sizes, int n_in,
                              void* d_out, int out_size) {
    const float* hidden = (const float*)d_in[0];
    const float* W_to   = (const float*)d_in[1];
    const float* b_to   = (const float*)d_in[2];
    const float* W_from = (const float*)d_in[3];
    const float* b_from = (const float*)d_in[4];
    const int*   token  = (const int*)d_in[5];
    const int*   ttid   = (const int*)d_in[6];

    const int P  = in_sizes[2];
    const int H  = in_sizes[4];
    const int BS = in_sizes[5];
    const int B  = out_size - BS * (P + H + 1);
    const int S  = BS / B;

    float* out = (float*)d_out;
    float* out_pr    = out;
    float* out_o     = out + (size_t)BS * P;
    float* out_mask  = out_o + (size_t)BS * H;
    float* out_usage = out_mask + BS;

    cudaFuncSetAttribute(gemm_tf32<false, false>,
                         cudaFuncAttributeMaxDynamicSharedMemorySize, SM_DYN);
    cudaFuncSetAttribute(gemm_tf32<true, true>,
                         cudaFuncAttributeMaxDynamicSharedMemorySize, SM_DYN);

    scan_kernel<<<1, 256>>>(token, ttid, out_usage, B, S);
    bcast_kernel<<<(BS + 255) / 256, 256>>>(out_mask, BS, S);
    conv_w_kernel<<<(H * P + 255) / 256, 256>>>(W_to, W_from, H, P);

    // GEMM1: PR = HS @ W_to + b_to   (M=BS, N=P, K=H)
    gemm_tf32<false, false><<<dim3(P / 128, BS / 128), 256, SM_DYN>>>(
        hidden, b_to, nullptr, out_pr, H, P, S);

    // GEMM2: OUT = blend(PR @ W_from + b_from, HS)  (M=BS, N=H, K=P)
    gemm_tf32<true, true><<<dim3(H / 128, BS / 128), 256, SM_DYN>>>(
        out_pr, b_from, hidden, out_o, P, H, S);
}

// round 13
// speedup vs baseline: 1.0952x; 1.0178x over previous
#include <cuda_runtime.h>
#include <cuda_bf16.h>
#include <cstdint>

// ===========================================================================
// InnerMonologue: single-pass TF32 GEMMs on mma.sync.m16n8k8.
// CTA 128x128, 512 threads (16 warps, 32x32 warp tiles), BK=32, 3-stage
// cp.async, register-double-buffered fragments (kp+1 loads overlap kp MMAs).
// Output: [PR (BS*P)] [OUT (BS*H)] [is_private (BS)] [usage (B)]  (all fp32)
// ===========================================================================

#define MAX_S 32768
#define MAX_WE (2048 * 256)

__device__ unsigned char g_mask[MAX_S];
__device__ float g_Wt[MAX_WE];  // W_to  transposed [P][H], tf32-rounded
__device__ float g_Wf[MAX_WE];  // W_from transposed [H][P], tf32-rounded

__device__ __forceinline__ uint32_t smem_u32(const void* p) {
    uint32_t a;
    asm("{ .reg .u64 t; cvta.to.shared.u64 t, %1; cvt.u32.u64 %0, t; }"
        : "=r"(a) : "l"(p));
    return a;
}
__device__ __forceinline__ void ldsm_x4(uint32_t addr, uint32_t* r) {
    asm volatile("ldmatrix.sync.aligned.m8n8.x4.shared.b16 {%0,%1,%2,%3}, [%4];"
                 : "=r"(r[0]), "=r"(r[1]), "=r"(r[2]), "=r"(r[3])
                 : "r"(addr));
}
__device__ __forceinline__ uint32_t cvt_tf32(uint32_t x) {
    uint32_t o;
    float f = __uint_as_float(x);
    asm("cvt.rna.tf32.f32 %0, %1;" : "=r"(o) : "f"(f));
    return o;
}
__device__ __forceinline__ void mma_tf32(float* c, const uint32_t* a,
                                         const uint32_t* b) {
    asm volatile(
        "mma.sync.aligned.m16n8k8.row.col.f32.tf32.tf32.f32 "
        "{%0,%1,%2,%3}, {%4,%5,%6,%7}, {%8,%9}, {%0,%1,%2,%3};"
        : "+f"(c[0]), "+f"(c[1]), "+f"(c[2]), "+f"(c[3])
        : "r"(a[0]), "r"(a[1]), "r"(a[2]), "r"(a[3]), "r"(b[0]), "r"(b[1]));
}
__device__ __forceinline__ void cp16(uint32_t dst, const void* src) {
    asm volatile("cp.async.cg.shared.global [%0], [%1], 16;"
                 :: "r"(dst), "l"(src));
}
#define CP_COMMIT() asm volatile("cp.async.commit_group;" ::: "memory")
#define CP_WAIT1()  asm volatile("cp.async.wait_group 1;" ::: "memory")

// SMEM rows: 32 fp32 (128B) + 16B pad = 144B stride -> conflict-free ldsm.
#define ROWB 144
#define TILE_B (128 * ROWB)            // 18432
#define STAGE_B (2 * TILE_B)           // 36864
#define ST_OFF(st) ((st) * STAGE_B)
#define SM_DYN (3 * STAGE_B)           // 110592

// ===========================================================================
// GEMM: C[128,128] = A[M,K]fp32 @ B[N,K]fp32(tf32)^T + bias (+mask blend).
// 512 threads, 16 warps (4x4), warp tile 32x32, BK=32, 3-stage cp.async,
// fragment double-buffering across k8 steps.
// ===========================================================================
template <bool MASKED, bool USE_WF>
__global__ void __launch_bounds__(512, 1)
gemm_tf32(const float* __restrict__ A, const float* __restrict__ bias,
          const float* __restrict__ HS, float* __restrict__ OUT,
          int K, int Ntot, int S) {
    extern __shared__ __align__(16) char smem[];
    __shared__ unsigned char smask[128];
    __shared__ int s_cnt;

    const float* __restrict__ Bw = USE_WF ? g_Wf : g_Wt;

    const int tid = threadIdx.x;
    const int wid = tid >> 5;
    const int lane = tid & 31;
    const int m0 = blockIdx.y * 128;
    const int n0 = blockIdx.x * 128;

    if (MASKED) {
        if (tid == 0) s_cnt = 0;
        __syncthreads();
        if (tid < 128) {
            unsigned char mm = g_mask[(m0 + tid) % S];
            smask[tid] = mm;
            if (mm) atomicAdd(&s_cnt, 1);
        }
        __syncthreads();
        if (s_cnt == 0) {  // all-public tile: straight copy of HS slab
            const size_t base = (size_t)m0 * Ntot + n0;
            for (int i = tid; i < 128 * 32; i += 512) {
                int r = i >> 5, c = (i & 31) << 2;
                *(float4*)&OUT[base + (size_t)r * Ntot + c] =
                    *(const float4*)&HS[base + (size_t)r * Ntot + c];
            }
            return;
        }
    }

    const uint32_t sbase = smem_u32(smem);
    const int wm = (wid >> 2) * 32;
    const int wn = (wid & 3) * 32;

    auto cp_stage = [&](int s, int st) {
        const int k0 = s << 5;
        const uint32_t dA = sbase + ST_OFF(st);
        const uint32_t dB = dA + TILE_B;
#pragma unroll
        for (int i = 0; i < 2; i++) {
            int u = tid * 2 + i;
            int row = u >> 3, col = u & 7;
            uint32_t doff = row * ROWB + col * 16;
            cp16(dA + doff, A + (size_t)(m0 + row) * K + k0 + col * 4);
            cp16(dB + doff, Bw + (size_t)(n0 + row) * K + k0 + col * 4);
        }
    };

    float acc[2][4][4];
#pragma unroll
    for (int mt = 0; mt < 2; mt++)
#pragma unroll
        for (int nt = 0; nt < 4; nt++)
#pragma unroll
            for (int i = 0; i < 4; i++) acc[mt][nt][i] = 0.f;

    const int r8 = lane & 7;
    const int mat = lane >> 3;  // 0..3
    const uint32_t aoff0 = (uint32_t)((wm + (mat & 1) * 8 + r8) * ROWB +
                                      (mat >> 1) * 16);
    const uint32_t boff0 = (uint32_t)((wn + (mat & 1) * 8 + r8) * ROWB +
                                      (mat >> 1) * 16);

    // Fragment load for one k8 step (no cvt here; cvt applied at use).
    auto load_frag = [&](uint32_t uA, uint32_t uB, int kp, uint32_t af[2][4],
                         uint32_t bf[2][4]) {
        const int kb = kp * 32;
        ldsm_x4(uA + aoff0 + kb, af[0]);
        ldsm_x4(uA + aoff0 + 16 * ROWB + kb, af[1]);
        ldsm_x4(uB + boff0 + kb, bf[0]);
        ldsm_x4(uB + boff0 + 16 * ROWB + kb, bf[1]);
    };
    auto do_mma = [&](uint32_t af[2][4], uint32_t bf[2][4]) {
#pragma unroll
        for (int mt = 0; mt < 2; mt++)
#pragma unroll
            for (int i = 0; i < 4; i++) af[mt][i] = cvt_tf32(af[mt][i]);
#pragma unroll
        for (int g = 0; g < 2; g++) {
            uint32_t b0[2] = {bf[g][0], bf[g][2]};  // n 0-7
            uint32_t b1[2] = {bf[g][1], bf[g][3]};  // n 8-15
#pragma unroll
            for (int mt = 0; mt < 2; mt++) {
                mma_tf32(acc[mt][2 * g], af[mt], b0);
                mma_tf32(acc[mt][2 * g + 1], af[mt], b1);
            }
        }
    };

    const int nk = K >> 5;
    cp_stage(0, 0); CP_COMMIT();
    cp_stage(1, 1); CP_COMMIT();
    int st = 0;
    uint32_t afA[2][4], bfA[2][4], afB[2][4], bfB[2][4];
    for (int s = 0; s < nk; s++) {
        CP_WAIT1();
        __syncthreads();
        if (s + 2 < nk) {
            int st2 = st + 2; if (st2 >= 3) st2 -= 3;
            cp_stage(s + 2, st2);
            CP_COMMIT();
        }
        const uint32_t uA = sbase + ST_OFF(st);
        const uint32_t uB = uA + TILE_B;
        // Software-pipelined k8 steps: load kp+1 before mma of kp.
        load_frag(uA, uB, 0, afA, bfA);
        load_frag(uA, uB, 1, afB, bfB);
        do_mma(afA, bfA);
        load_frag(uA, uB, 2, afA, bfA);
        do_mma(afB, bfB);
        load_frag(uA, uB, 3, afB, bfB);
        do_mma(afA, bfA);
        do_mma(afB, bfB);
        if (++st == 3) st = 0;
    }

    // ---- Epilogue ----
    const int qr = lane >> 2;
    const int qc = (lane & 3) * 2;
#pragma unroll
    for (int mt = 0; mt < 2; mt++) {
        const int lr0 = wm + mt * 16 + qr;
        const int lr1 = lr0 + 8;
        const size_t rb0 = (size_t)(m0 + lr0) * Ntot;
        const size_t rb1 = (size_t)(m0 + lr1) * Ntot;
        const bool p0 = !MASKED || (smask[lr0] != 0);
        const bool p1 = !MASKED || (smask[lr1] != 0);
#pragma unroll
        for (int nt = 0; nt < 4; nt++) {
            const int col = n0 + wn + nt * 8 + qc;
            float2 b2 = *(const float2*)&bias[col];
            float2 v0, v1;
            v0.x = acc[mt][nt][0] + b2.x;
            v0.y = acc[mt][nt][1] + b2.y;
            v1.x = acc[mt][nt][2] + b2.x;
            v1.y = acc[mt][nt][3] + b2.y;
            if (MASKED) {
                if (!p0) v0 = *(const float2*)&HS[rb0 + col];
                if (!p1) v1 = *(const float2*)&HS[rb1 + col];
            }
            *(float2*)&OUT[rb0 + col] = v0;
            *(float2*)&OUT[rb1 + col] = v1;
        }
    }
}

// ===========================================================================
// Mask scan, broadcast, weight transpose (+tf32 pre-round) kernels.
// ===========================================================================
__global__ void scan_kernel(const int* __restrict__ tok,
                            const int* __restrict__ ttid_p,
                            float* __restrict__ usage_out, int B, int S) {
    __shared__ int stok[8192];
    __shared__ int sc[256];
    const int ttid = *ttid_p;
    const int tid = threadIdx.x;
    const bool fits = (S <= 8192);
    if (fits)
        for (int i = tid; i < S; i += 256) stok[i] = tok[i];
    __syncthreads();
    const int* src = fits ? stok : tok;

    const int chunk = (S + 255) / 256;
    const int start = tid * chunk;
    const int end = min(start + chunk, S);
    int cnt = 0;
    for (int i = start; i < end; i++) cnt += (src[i] == ttid);
    sc[tid] = cnt;
    __syncthreads();
    for (int off = 1; off < 256; off <<= 1) {
        int v = (tid >= off) ? sc[tid - off] : 0;
        __syncthreads();
        sc[tid] += v;
        __syncthreads();
    }
    int run = sc[tid] - cnt;
    int ones = 0;
    for (int i = start; i < end; i++) {
        run += (src[i] == ttid);
        unsigned char m = (unsigned char)(run & 1);
        g_mask[i] = m;
        ones += m;
    }
    __syncthreads();
    sc[tid] = ones;
    __syncthreads();
    for (int off = 128; off > 0; off >>= 1) {
        if (tid < off) sc[tid] += sc[tid + off];
        __syncthreads();
    }
    if (tid < B) usage_out[tid] = (float)sc[0] / (float)S;
}

__global__ void bcast_kernel(float* __restrict__ out_mask, int BS, int S) {
    int i = blockIdx.x * blockDim.x + threadIdx.x;
    if (i < BS) out_mask[i] = (float)g_mask[i % S];
}

__device__ __forceinline__ float round_tf32(float v) {
    uint32_t o;
    asm("cvt.rna.tf32.f32 %0, %1;" : "=r"(o) : "f"(v));
    return __uint_as_float(o);
}

__global__ void conv_w_kernel(const float* __restrict__ W_to,
                              const float* __restrict__ W_from, int H, int P) {
    int idx = blockIdx.x * blockDim.x + threadIdx.x;
    if (idx >= H * P) return;
    {  // W_to [H][P] -> Wt [P][H], tf32-rounded
        int k = idx / P, n = idx - k * P;
        g_Wt[n * H + k] = round_tf32(W_to[idx]);
    }
    {  // W_from [P][H] -> Wf [H][P], tf32-rounded
        int p = idx / H, hh = idx - p * H;
        g_Wf[hh * P + p] = round_tf32(W_from[idx]);
    }
}

// ===========================================================================
extern "C" void kernel_launch(void* const* d_in, const int* in_sizes, int n_in,
                              void* d_out, int out_size) {
    const float* hidden = (const float*)d_in[0];
    const float* W_to   = (const float*)d_in[1];
    const float* b_to   = (const float*)d_in[2];
    const float* W_from = (const float*)d_in[3];
    const float* b_from = (const float*)d_in[4];
    const int*   token  = (const int*)d_in[5];
    const int*   ttid   = (const int*)d_in[6];

    const int P  = in_sizes[2];
    const int H  = in_sizes[4];
    const int BS = in_sizes[5];
    const int B  = out_size - BS * (P + H + 1);
    const int S  = BS / B;

    float* out = (float*)d_out;
    float* out_pr    = out;
    float* out_o     = out + (size_t)BS * P;
    float* out_mask  = out_o + (size_t)BS * H;
    float* out_usage = out_mask + BS;

    cudaFuncSetAttribute(gemm_tf32<false, false>,
                         cudaFuncAttributeMaxDynamicSharedMemorySize, SM_DYN);
    cudaFuncSetAttribute(gemm_tf32<true, true>,
                         cudaFuncAttributeMaxDynamicSharedMemorySize, SM_DYN);

    scan_kernel<<<1, 256>>>(token, ttid, out_usage, B, S);
    bcast_kernel<<<(BS + 255) / 256, 256>>>(out_mask, BS, S);
    conv_w_kernel<<<(H * P + 255) / 256, 256>>>(W_to, W_from, H, P);

    // GEMM1: PR = HS @ W_to + b_to   (M=BS, N=P, K=H)
    gemm_tf32<false, false><<<dim3(P / 128, BS / 128), 512, SM_DYN>>>(
        hidden, b_to, nullptr, out_pr, H, P, S);

    // GEMM2: OUT = blend(PR @ W_from + b_from, HS)  (M=BS, N=H, K=P)
    gemm_tf32<true, true><<<dim3(H / 128, BS / 128), 512, SM_DYN>>>(
        out_pr, b_from, hidden, out_o, P, H, S);
}

// round 14
// speedup vs baseline: 1.6157x; 1.4752x over previous
#include <cuda_runtime.h>
#include <cuda_fp16.h>
#include <cstdint>

// ===========================================================================
// InnerMonologue: single-pass FP16 GEMMs on mma.sync.m16n8k16 (2x tf32 rate,
// same 11-bit mantissa). Operands pre-converted to fp16 in gmem; hot loop is
// pure cp.async + ldsm + mma. CTA 128x128, 16 warps 32x32, BK=64, 3 stages.
// Output: [PR (BS*P)] [OUT (BS*H)] [is_private (BS)] [usage (B)]  (all fp32)
// ===========================================================================

#define MAX_S 32768
#define MAX_WE (2048 * 256)
#define MAX_HS (32768 * 2048)
#define MAX_PR (32768 * 256)

__device__ unsigned char g_mask[MAX_S];
__device__ __half g_Wt16[MAX_WE];   // W_to  transposed [P][H] fp16
__device__ __half g_Wf16[MAX_WE];   // W_from transposed [H][P] fp16
__device__ __half g_H16[MAX_HS];    // hidden fp16 [BS][H]
__device__ __half g_PR16[MAX_PR];   // PR fp16 [BS][P] (written by GEMM1)

__device__ __forceinline__ uint32_t smem_u32(const void* p) {
    uint32_t a;
    asm("{ .reg .u64 t; cvta.to.shared.u64 t, %1; cvt.u32.u64 %0, t; }"
        : "=r"(a) : "l"(p));
    return a;
}
__device__ __forceinline__ void ldsm_x4(uint32_t addr, uint32_t* r) {
    asm volatile("ldmatrix.sync.aligned.m8n8.x4.shared.b16 {%0,%1,%2,%3}, [%4];"
                 : "=r"(r[0]), "=r"(r[1]), "=r"(r[2]), "=r"(r[3])
                 : "r"(addr));
}
__device__ __forceinline__ void mma_f16(float* c, const uint32_t* a,
                                        const uint32_t* b) {
    asm volatile(
        "mma.sync.aligned.m16n8k16.row.col.f32.f16.f16.f32 "
        "{%0,%1,%2,%3}, {%4,%5,%6,%7}, {%8,%9}, {%0,%1,%2,%3};"
        : "+f"(c[0]), "+f"(c[1]), "+f"(c[2]), "+f"(c[3])
        : "r"(a[0]), "r"(a[1]), "r"(a[2]), "r"(a[3]), "r"(b[0]), "r"(b[1]));
}
__device__ __forceinline__ void cp16(uint32_t dst, const void* src) {
    asm volatile("cp.async.cg.shared.global [%0], [%1], 16;"
                 :: "r"(dst), "l"(src));
}
#define CP_COMMIT() asm volatile("cp.async.commit_group;" ::: "memory")
#define CP_WAIT1()  asm volatile("cp.async.wait_group 1;" ::: "memory")

// SMEM rows: 64 fp16 (128B) + 16B pad = 144B stride -> conflict-free ldsm.
#define ROWB 144
#define TILE_B (128 * ROWB)            // 18432
#define STAGE_B (2 * TILE_B)           // 36864
#define ST_OFF(st) ((st) * STAGE_B)
#define SM_DYN (3 * STAGE_B)           // 110592

// ===========================================================================
// GEMM: C[128,128] = A[M,K]fp16 @ B[N,K]fp16^T + bias (+blend / +fp16 out).
// 512 threads, 16 warps (4x4), warp tile 32x32, BK=64, 3-stage cp.async.
// ===========================================================================
template <bool MASKED, bool USE_WF, bool USE_PR_A, bool WRITE_F16>
__global__ void __launch_bounds__(512, 1)
gemm_f16(const float* __restrict__ bias, const float* __restrict__ HS,
         float* __restrict__ OUT, int K, int Ntot, int S) {
    extern __shared__ __align__(16) char smem[];
    __shared__ unsigned char smask[128];
    __shared__ int s_cnt;

    const __half* __restrict__ Ah = USE_PR_A ? g_PR16 : g_H16;
    const __half* __restrict__ Bw = USE_WF ? g_Wf16 : g_Wt16;

    const int tid = threadIdx.x;
    const int wid = tid >> 5;
    const int lane = tid & 31;
    const int m0 = blockIdx.y * 128;
    const int n0 = blockIdx.x * 128;

    if (MASKED) {
        if (tid == 0) s_cnt = 0;
        __syncthreads();
        if (tid < 128) {
            unsigned char mm = g_mask[(m0 + tid) % S];
            smask[tid] = mm;
            if (mm) atomicAdd(&s_cnt, 1);
        }
        __syncthreads();
        if (s_cnt == 0) {  // all-public tile: straight copy of HS slab
            const size_t base = (size_t)m0 * Ntot + n0;
            for (int i = tid; i < 128 * 32; i += 512) {
                int r = i >> 5, c = (i & 31) << 2;
                *(float4*)&OUT[base + (size_t)r * Ntot + c] =
                    *(const float4*)&HS[base + (size_t)r * Ntot + c];
            }
            return;
        }
    }

    const uint32_t sbase = smem_u32(smem);
    const int wm = (wid >> 2) * 32;
    const int wn = (wid & 3) * 32;

    // cp.async: A tile 128 rows x 8 16B-units = 1024 (2/thread), B same.
    auto cp_stage = [&](int s, int st) {
        const int k0 = s << 6;
        const uint32_t dA = sbase + ST_OFF(st);
        const uint32_t dB = dA + TILE_B;
#pragma unroll
        for (int i = 0; i < 2; i++) {
            int u = tid * 2 + i;
            int row = u >> 3, col = u & 7;
            uint32_t doff = row * ROWB + col * 16;
            cp16(dA + doff, Ah + (size_t)(m0 + row) * K + k0 + col * 8);
            cp16(dB + doff, Bw + (size_t)(n0 + row) * K + k0 + col * 8);
        }
    };

    float acc[2][4][4];
#pragma unroll
    for (int mt = 0; mt < 2; mt++)
#pragma unroll
        for (int nt = 0; nt < 4; nt++)
#pragma unroll
            for (int i = 0; i < 4; i++) acc[mt][nt][i] = 0.f;

    const int r8 = lane & 7;
    const int mat = lane >> 3;  // 0..3
    // ldsm x4 tile: rows +(mat&1)*8, k16 half selected by (mat>>1)*16B.
    const uint32_t aoff0 = (uint32_t)((wm + (mat & 1) * 8 + r8) * ROWB +
                                      (mat >> 1) * 16);
    const uint32_t boff0 = (uint32_t)((wn + (mat & 1) * 8 + r8) * ROWB +
                                      (mat >> 1) * 16);

    auto compute = [&](int st) {
        const uint32_t uA = sbase + ST_OFF(st);
        const uint32_t uB = uA + TILE_B;
#pragma unroll
        for (int ks = 0; ks < 4; ks++) {  // four k16 steps per BK=64
            const int kb = ks * 32;       // 16 fp16 = 32B
            uint32_t af[2][4], bf[2][4];
#pragma unroll
            for (int mt = 0; mt < 2; mt++)
                ldsm_x4(uA + aoff0 + mt * 16 * ROWB + kb, af[mt]);
#pragma unroll
            for (int g = 0; g < 2; g++)
                ldsm_x4(uB + boff0 + g * 16 * ROWB + kb, bf[g]);
#pragma unroll
            for (int g = 0; g < 2; g++) {
                uint32_t b0[2] = {bf[g][0], bf[g][2]};  // n 0-7
                uint32_t b1[2] = {bf[g][1], bf[g][3]};  // n 8-15
#pragma unroll
                for (int mt = 0; mt < 2; mt++) {
                    mma_f16(acc[mt][2 * g], af[mt], b0);
                    mma_f16(acc[mt][2 * g + 1], af[mt], b1);
                }
            }
        }
    };

    const int nk = K >> 6;
    cp_stage(0, 0); CP_COMMIT();
    if (nk > 1) { cp_stage(1, 1); } CP_COMMIT();
    int st = 0;
    for (int s = 0; s < nk; s++) {
        CP_WAIT1();
        __syncthreads();
        if (s + 2 < nk) {
            int st2 = st + 2; if (st2 >= 3) st2 -= 3;
            cp_stage(s + 2, st2);
            CP_COMMIT();
        } else {
            CP_COMMIT();  // keep group count balanced for CP_WAIT1
        }
        compute(st);
        if (++st == 3) st = 0;
    }

    // ---- Epilogue ----
    const int qr = lane >> 2;
    const int qc = (lane & 3) * 2;
#pragma unroll
    for (int mt = 0; mt < 2; mt++) {
        const int lr0 = wm + mt * 16 + qr;
        const int lr1 = lr0 + 8;
        const size_t rb0 = (size_t)(m0 + lr0) * Ntot;
        const size_t rb1 = (size_t)(m0 + lr1) * Ntot;
        const bool p0 = !MASKED || (smask[lr0] != 0);
        const bool p1 = !MASKED || (smask[lr1] != 0);
#pragma unroll
        for (int nt = 0; nt < 4; nt++) {
            const int col = n0 + wn + nt * 8 + qc;
            float2 b2 = *(const float2*)&bias[col];
            float2 v0, v1;
            v0.x = acc[mt][nt][0] + b2.x;
            v0.y = acc[mt][nt][1] + b2.y;
            v1.x = acc[mt][nt][2] + b2.x;
            v1.y = acc[mt][nt][3] + b2.y;
            if (WRITE_F16) {  // GEMM1: also emit fp16 PR for GEMM2's A
                __half2 h0 = __floats2half2_rn(v0.x, v0.y);
                __half2 h1 = __floats2half2_rn(v1.x, v1.y);
                *(__half2*)&g_PR16[rb0 + col] = h0;
                *(__half2*)&g_PR16[rb1 + col] = h1;
            }
            if (MASKED) {
                if (!p0) v0 = *(const float2*)&HS[rb0 + col];
                if (!p1) v1 = *(const float2*)&HS[rb1 + col];
            }
            *(float2*)&OUT[rb0 + col] = v0;
            *(float2*)&OUT[rb1 + col] = v1;
        }
    }
}

// ===========================================================================
// hidden fp32 -> fp16 (streaming, 8 elems/thread)
// ===========================================================================
__global__ void h2_kernel(const float* __restrict__ src, int n) {
    int i = (blockIdx.x * blockDim.x + threadIdx.x) * 8;
    if (i >= n) return;
    float4 v0 = *(const float4*)(src + i);
    float4 v1 = *(const float4*)(src + i + 4);
    __half2 h[4];
    h[0] = __floats2half2_rn(v0.x, v0.y);
    h[1] = __floats2half2_rn(v0.z, v0.w);
    h[2] = __floats2half2_rn(v1.x, v1.y);
    h[3] = __floats2half2_rn(v1.z, v1.w);
    *(uint4*)&g_H16[i] = *(uint4*)h;
}

// ===========================================================================
// Mask scan, broadcast, weight transpose+fp16 kernels.
// ===========================================================================
__global__ void scan_kernel(const int* __restrict__ tok,
                            const int* __restrict__ ttid_p,
                            float* __restrict__ usage_out, int B, int S) {
    __shared__ int stok[8192];
    __shared__ int sc[256];
    const int ttid = *ttid_p;
    const int tid = threadIdx.x;
    const bool fits = (S <= 8192);
    if (fits)
        for (int i = tid; i < S; i += 256) stok[i] = tok[i];
    __syncthreads();
    const int* src = fits ? stok : tok;

    const int chunk = (S + 255) / 256;
    const int start = tid * chunk;
    const int end = min(start + chunk, S);
    int cnt = 0;
    for (int i = start; i < end; i++) cnt += (src[i] == ttid);
    sc[tid] = cnt;
    __syncthreads();
    for (int off = 1; off < 256; off <<= 1) {
        int v = (tid >= off) ? sc[tid - off] : 0;
        __syncthreads();
        sc[tid] += v;
        __syncthreads();
    }
    int run = sc[tid] - cnt;
    int ones = 0;
    for (int i = start; i < end; i++) {
        run += (src[i] == ttid);
        unsigned char m = (unsigned char)(run & 1);
        g_mask[i] = m;
        ones += m;
    }
    __syncthreads();
    sc[tid] = ones;
    __syncthreads();
    for (int off = 128; off > 0; off >>= 1) {
        if (tid < off) sc[tid] += sc[tid + off];
        __syncthreads();
    }
    if (tid < B) usage_out[tid] = (float)sc[0] / (float)S;
}

__global__ void bcast_kernel(float* __restrict__ out_mask, int BS, int S) {
    int i = blockIdx.x * blockDim.x + threadIdx.x;
    if (i < BS) out_mask[i] = (float)g_mask[i % S];
}

__global__ void conv_w_kernel(const float* __restrict__ W_to,
                              const float* __restrict__ W_from, int H, int P) {
    int idx = blockIdx.x * blockDim.x + threadIdx.x;
    if (idx >= H * P) return;
    {  // W_to [H][P] -> Wt [P][H] fp16
        int k = idx / P, n = idx - k * P;
        g_Wt16[n * H + k] = __float2half_rn(W_to[idx]);
    }
    {  // W_from [P][H] -> Wf [H][P] fp16
        int p = idx / H, hh = idx - p * H;
        g_Wf16[hh * P + p] = __float2half_rn(W_from[idx]);
    }
}

// ===========================================================================
extern "C" void kernel_launch(void* const* d_in, const int* in_sizes, int n_in,
                              void* d_out, int out_size) {
    const float* hidden = (const float*)d_in[0];
    const float* W_to   = (const float*)d_in[1];
    const float* b_to   = (const float*)d_in[2];
    const float* W_from = (const float*)d_in[3];
    const float* b_from = (const float*)d_in[4];
    const int*   token  = (const int*)d_in[5];
    const int*   ttid   = (const int*)d_in[6];

    const int P  = in_sizes[2];
    const int H  = in_sizes[4];
    const int BS = in_sizes[5];
    const int B  = out_size - BS * (P + H + 1);
    const int S  = BS / B;

    float* out = (float*)d_out;
    float* out_pr    = out;
    float* out_o     = out + (size_t)BS * P;
    float* out_mask  = out_o + (size_t)BS * H;
    float* out_usage = out_mask + BS;

    cudaFuncSetAttribute(gemm_f16<false, false, false, true>,
                         cudaFuncAttributeMaxDynamicSharedMemorySize, SM_DYN);
    cudaFuncSetAttribute(gemm_f16<true, true, true, false>,
                         cudaFuncAttributeMaxDynamicSharedMemorySize, SM_DYN);

    scan_kernel<<<1, 256>>>(token, ttid, out_usage, B, S);
    bcast_kernel<<<(BS + 255) / 256, 256>>>(out_mask, BS, S);
    conv_w_kernel<<<(H * P + 255) / 256, 256>>>(W_to, W_from, H, P);
    h2_kernel<<<(BS * H / 8 + 255) / 256, 256>>>(hidden, BS * H);

    // GEMM1: PR = HS @ W_to + b_to   (M=BS, N=P, K=H); writes fp16 PR too
    gemm_f16<false, false, false, true>
        <<<dim3(P / 128, BS / 128), 512, SM_DYN>>>(
            b_to, nullptr, out_pr, H, P, S);

    // GEMM2: OUT = blend(PR @ W_from + b_from, HS)  (M=BS, N=H, K=P)
    gemm_f16<true, true, true, false>
        <<<dim3(H / 128, BS / 128), 512, SM_DYN>>>(
            b_from, hidden, out_o, P, H, S);
}

// round 15
// speedup vs baseline: 1.6850x; 1.0429x over previous
#include <cuda_runtime.h>
#include <cuda_fp16.h>
#include <cstdint>

// ===========================================================================
// InnerMonologue: FP16 GEMMs on mma.sync.m16n8k16.
// CTA 128x256, 16 warps (4x4) of 32x64, BK=64, 3-stage cp.async (162KB).
// Operands pre-converted to fp16 in gmem; hot loop pure cp.async+ldsm+mma.
// Output: [PR (BS*P)] [OUT (BS*H)] [is_private (BS)] [usage (B)]  (all fp32)
// ===========================================================================

#define MAX_S 32768
#define MAX_WE (2048 * 256)
#define MAX_HS (32768 * 2048)
#define MAX_PR (32768 * 256)

__device__ unsigned char g_mask[MAX_S];
__device__ __half g_Wt16[MAX_WE];   // W_to  transposed [P][H] fp16
__device__ __half g_Wf16[MAX_WE];   // W_from transposed [H][P] fp16
__device__ __half g_H16[MAX_HS];    // hidden fp16 [BS][H]
__device__ __half g_PR16[MAX_PR];   // PR fp16 [BS][P] (written by GEMM1)

__device__ __forceinline__ uint32_t smem_u32(const void* p) {
    uint32_t a;
    asm("{ .reg .u64 t; cvta.to.shared.u64 t, %1; cvt.u32.u64 %0, t; }"
        : "=r"(a) : "l"(p));
    return a;
}
__device__ __forceinline__ void ldsm_x4(uint32_t addr, uint32_t* r) {
    asm volatile("ldmatrix.sync.aligned.m8n8.x4.shared.b16 {%0,%1,%2,%3}, [%4];"
                 : "=r"(r[0]), "=r"(r[1]), "=r"(r[2]), "=r"(r[3])
                 : "r"(addr));
}
__device__ __forceinline__ void mma_f16(float* c, const uint32_t* a,
                                        const uint32_t* b) {
    asm volatile(
        "mma.sync.aligned.m16n8k16.row.col.f32.f16.f16.f32 "
        "{%0,%1,%2,%3}, {%4,%5,%6,%7}, {%8,%9}, {%0,%1,%2,%3};"
        : "+f"(c[0]), "+f"(c[1]), "+f"(c[2]), "+f"(c[3])
        : "r"(a[0]), "r"(a[1]), "r"(a[2]), "r"(a[3]), "r"(b[0]), "r"(b[1]));
}
__device__ __forceinline__ void cp16(uint32_t dst, const void* src) {
    asm volatile("cp.async.cg.shared.global [%0], [%1], 16;"
                 :: "r"(dst), "l"(src));
}
#define CP_COMMIT() asm volatile("cp.async.commit_group;" ::: "memory")
#define CP_WAIT1()  asm volatile("cp.async.wait_group 1;" ::: "memory")

// SMEM rows: 64 fp16 (128B) + 16B pad = 144B stride -> conflict-free ldsm.
#define ROWB 144
#define A_T (128 * ROWB)               // 18432
#define B_T (256 * ROWB)               // 36864
#define STAGE_B (A_T + B_T)            // 55296
#define ST_OFF(st) ((st) * STAGE_B)
#define SM_DYN (3 * STAGE_B)           // 165888 (162KB)

// ===========================================================================
// GEMM: C[128,256] = A[M,K]fp16 @ B[N,K]fp16^T + bias (+blend / +fp16 out).
// 512 threads, 16 warps (4M x 4N), warp tile 32x64, BK=64, 3-stage cp.async.
// ===========================================================================
template <bool MASKED, bool USE_WF, bool USE_PR_A, bool WRITE_F16>
__global__ void __launch_bounds__(512, 1)
gemm_f16(const float* __restrict__ bias, const float* __restrict__ HS,
         float* __restrict__ OUT, int K, int Ntot, int S) {
    extern __shared__ __align__(16) char smem[];
    __shared__ unsigned char smask[128];
    __shared__ int s_cnt;

    const __half* __restrict__ Ah = USE_PR_A ? g_PR16 : g_H16;
    const __half* __restrict__ Bw = USE_WF ? g_Wf16 : g_Wt16;

    const int tid = threadIdx.x;
    const int wid = tid >> 5;
    const int lane = tid & 31;
    const int m0 = blockIdx.y * 128;
    const int n0 = blockIdx.x * 256;

    if (MASKED) {
        if (tid == 0) s_cnt = 0;
        __syncthreads();
        if (tid < 128) {
            unsigned char mm = g_mask[(m0 + tid) % S];
            smask[tid] = mm;
            if (mm) atomicAdd(&s_cnt, 1);
        }
        __syncthreads();
        if (s_cnt == 0) {  // all-public tile: straight copy of HS slab
            const size_t base = (size_t)m0 * Ntot + n0;
            for (int i = tid; i < 128 * 64; i += 512) {
                int r = i >> 6, c = (i & 63) << 2;
                *(float4*)&OUT[base + (size_t)r * Ntot + c] =
                    *(const float4*)&HS[base + (size_t)r * Ntot + c];
            }
            return;
        }
    }

    const uint32_t sbase = smem_u32(smem);
    const int wm = (wid >> 2) * 32;   // 4 warp rows
    const int wn = (wid & 3) * 64;    // 4 warp cols (64 wide)

    // cp.async: A 128 rows x 8 units = 1024 (2/thread), B 256 rows = 2048
    // (4/thread).
    auto cp_stage = [&](int s, int st) {
        const int k0 = s << 6;
        const uint32_t dA = sbase + ST_OFF(st);
        const uint32_t dB = dA + A_T;
#pragma unroll
        for (int i = 0; i < 2; i++) {
            int u = tid * 2 + i;
            int row = u >> 3, col = u & 7;
            cp16(dA + row * ROWB + col * 16,
                 Ah + (size_t)(m0 + row) * K + k0 + col * 8);
        }
#pragma unroll
        for (int i = 0; i < 4; i++) {
            int u = tid * 4 + i;
            int row = u >> 3, col = u & 7;
            cp16(dB + row * ROWB + col * 16,
                 Bw + (size_t)(n0 + row) * K + k0 + col * 8);
        }
    };

    float acc[2][8][4];
#pragma unroll
    for (int mt = 0; mt < 2; mt++)
#pragma unroll
        for (int nt = 0; nt < 8; nt++)
#pragma unroll
            for (int i = 0; i < 4; i++) acc[mt][nt][i] = 0.f;

    const int r8 = lane & 7;
    const int mat = lane >> 3;  // 0..3
    const uint32_t aoff0 = (uint32_t)((wm + (mat & 1) * 8 + r8) * ROWB +
                                      (mat >> 1) * 16);
    const uint32_t boff0 = (uint32_t)((wn + (mat & 1) * 8 + r8) * ROWB +
                                      (mat >> 1) * 16);

    auto compute = [&](int st) {
        const uint32_t uA = sbase + ST_OFF(st);
        const uint32_t uB = uA + A_T;
#pragma unroll
        for (int ks = 0; ks < 4; ks++) {  // four k16 steps per BK=64
            const int kb = ks * 32;       // 16 fp16 = 32B
            uint32_t af[2][4], bf[4][4];
#pragma unroll
            for (int mt = 0; mt < 2; mt++)
                ldsm_x4(uA + aoff0 + mt * 16 * ROWB + kb, af[mt]);
#pragma unroll
            for (int g = 0; g < 4; g++)
                ldsm_x4(uB + boff0 + g * 16 * ROWB + kb, bf[g]);
#pragma unroll
            for (int g = 0; g < 4; g++) {
                uint32_t b0[2] = {bf[g][0], bf[g][2]};  // n 0-7
                uint32_t b1[2] = {bf[g][1], bf[g][3]};  // n 8-15
#pragma unroll
                for (int mt = 0; mt < 2; mt++) {
                    mma_f16(acc[mt][2 * g], af[mt], b0);
                    mma_f16(acc[mt][2 * g + 1], af[mt], b1);
                }
            }
        }
    };

    const int nk = K >> 6;
    cp_stage(0, 0); CP_COMMIT();
    if (nk > 1) { cp_stage(1, 1); } CP_COMMIT();
    int st = 0;
    for (int s = 0; s < nk; s++) {
        CP_WAIT1();
        __syncthreads();
        if (s + 2 < nk) {
            int st2 = st + 2; if (st2 >= 3) st2 -= 3;
            cp_stage(s + 2, st2);
            CP_COMMIT();
        } else {
            CP_COMMIT();  // keep group count balanced for CP_WAIT1
        }
        compute(st);
        if (++st == 3) st = 0;
    }

    // ---- Epilogue ----
    const int qr = lane >> 2;
    const int qc = (lane & 3) * 2;
#pragma unroll
    for (int mt = 0; mt < 2; mt++) {
        const int lr0 = wm + mt * 16 + qr;
        const int lr1 = lr0 + 8;
        const size_t rb0 = (size_t)(m0 + lr0) * Ntot;
        const size_t rb1 = (size_t)(m0 + lr1) * Ntot;
        const bool p0 = !MASKED || (smask[lr0] != 0);
        const bool p1 = !MASKED || (smask[lr1] != 0);
#pragma unroll
        for (int nt = 0; nt < 8; nt++) {
            const int col = n0 + wn + nt * 8 + qc;
            float2 b2 = *(const float2*)&bias[col];
            float2 v0, v1;
            v0.x = acc[mt][nt][0] + b2.x;
            v0.y = acc[mt][nt][1] + b2.y;
            v1.x = acc[mt][nt][2] + b2.x;
            v1.y = acc[mt][nt][3] + b2.y;
            if (WRITE_F16) {  // GEMM1: also emit fp16 PR for GEMM2's A
                *(__half2*)&g_PR16[rb0 + col] = __floats2half2_rn(v0.x, v0.y);
                *(__half2*)&g_PR16[rb1 + col] = __floats2half2_rn(v1.x, v1.y);
            }
            if (MASKED) {
                if (!p0) v0 = *(const float2*)&HS[rb0 + col];
                if (!p1) v1 = *(const float2*)&HS[rb1 + col];
            }
            *(float2*)&OUT[rb0 + col] = v0;
            *(float2*)&OUT[rb1 + col] = v1;
        }
    }
}

// ===========================================================================
// hidden fp32 -> fp16 (streaming, 8 elems/thread)
// ===========================================================================
__global__ void h2_kernel(const float* __restrict__ src, int n) {
    int i = (blockIdx.x * blockDim.x + threadIdx.x) * 8;
    if (i >= n) return;
    float4 v0 = *(const float4*)(src + i);
    float4 v1 = *(const float4*)(src + i + 4);
    __half2 h[4];
    h[0] = __floats2half2_rn(v0.x, v0.y);
    h[1] = __floats2half2_rn(v0.z, v0.w);
    h[2] = __floats2half2_rn(v1.x, v1.y);
    h[3] = __floats2half2_rn(v1.z, v1.w);
    *(uint4*)&g_H16[i] = *(uint4*)h;
}

// ===========================================================================
// Mask scan, broadcast, weight transpose+fp16 kernels.
// ===========================================================================
__global__ void scan_kernel(const int* __restrict__ tok,
                            const int* __restrict__ ttid_p,
                            float* __restrict__ usage_out, int B, int S) {
    __shared__ int stok[8192];
    __shared__ int sc[256];
    const int ttid = *ttid_p;
    const int tid = threadIdx.x;
    const bool fits = (S <= 8192);
    if (fits)
        for (int i = tid; i < S; i += 256) stok[i] = tok[i];
    __syncthreads();
    const int* src = fits ? stok : tok;

    const int chunk = (S + 255) / 256;
    const int start = tid * chunk;
    const int end = min(start + chunk, S);
    int cnt = 0;
    for (int i = start; i < end; i++) cnt += (src[i] == ttid);
    sc[tid] = cnt;
    __syncthreads();
    for (int off = 1; off < 256; off <<= 1) {
        int v = (tid >= off) ? sc[tid - off] : 0;
        __syncthreads();
        sc[tid] += v;
        __syncthreads();
    }
    int run = sc[tid] - cnt;
    int ones = 0;
    for (int i = start; i < end; i++) {
        run += (src[i] == ttid);
        unsigned char m = (unsigned char)(run & 1);
        g_mask[i] = m;
        ones += m;
    }
    __syncthreads();
    sc[tid] = ones;
    __syncthreads();
    for (int off = 128; off > 0; off >>= 1) {
        if (tid < off) sc[tid] += sc[tid + off];
        __syncthreads();
    }
    if (tid < B) usage_out[tid] = (float)sc[0] / (float)S;
}

__global__ void bcast_kernel(float* __restrict__ out_mask, int BS, int S) {
    int i = blockIdx.x * blockDim.x + threadIdx.x;
    if (i < BS) out_mask[i] = (float)g_mask[i % S];
}

__global__ void conv_w_kernel(const float* __restrict__ W_to,
                              const float* __restrict__ W_from, int H, int P) {
    int idx = blockIdx.x * blockDim.x + threadIdx.x;
    if (idx >= H * P) return;
    {  // W_to [H][P] -> Wt [P][H] fp16
        int k = idx / P, n = idx - k * P;
        g_Wt16[n * H + k] = __float2half_rn(W_to[idx]);
    }
    {  // W_from [P][H] -> Wf [H][P] fp16
        int p = idx / H, hh = idx - p * H;
        g_Wf16[hh * P + p] = __float2half_rn(W_from[idx]);
    }
}

// ===========================================================================
extern "C" void kernel_launch(void* const* d_in, const int* in_sizes, int n_in,
                              void* d_out, int out_size) {
    const float* hidden = (const float*)d_in[0];
    const float* W_to   = (const float*)d_in[1];
    const float* b_to   = (const float*)d_in[2];
    const float* W_from = (const float*)d_in[3];
    const float* b_from = (const float*)d_in[4];
    const int*   token  = (const int*)d_in[5];
    const int*   ttid   = (const int*)d_in[6];

    const int P  = in_sizes[2];
    const int H  = in_sizes[4];
    const int BS = in_sizes[5];
    const int B  = out_size - BS * (P + H + 1);
    const int S  = BS / B;

    float* out = (float*)d_out;
    float* out_pr    = out;
    float* out_o     = out + (size_t)BS * P;
    float* out_mask  = out_o + (size_t)BS * H;
    float* out_usage = out_mask + BS;

    cudaFuncSetAttribute(gemm_f16<false, false, false, true>,
                         cudaFuncAttributeMaxDynamicSharedMemorySize, SM_DYN);
    cudaFuncSetAttribute(gemm_f16<true, true, true, false>,
                         cudaFuncAttributeMaxDynamicSharedMemorySize, SM_DYN);

    scan_kernel<<<1, 256>>>(token, ttid, out_usage, B, S);
    bcast_kernel<<<(BS + 255) / 256, 256>>>(out_mask, BS, S);
    conv_w_kernel<<<(H * P + 255) / 256, 256>>>(W_to, W_from, H, P);
    h2_kernel<<<(BS * H / 8 + 255) / 256, 256>>>(hidden, BS * H);

    // GEMM1: PR = HS @ W_to + b_to   (M=BS, N=P=256 -> 1 n-block, K=H)
    gemm_f16<false, false, false, true>
        <<<dim3(P / 256, BS / 128), 512, SM_DYN>>>(
            b_to, nullptr, out_pr, H, P, S);

    // GEMM2: OUT = blend(PR @ W_from + b_from, HS)  (M=BS, N=H, K=P)
    gemm_f16<true, true, true, false>
        <<<dim3(H / 256, BS / 128), 512, SM_DYN>>>(
            b_from, hidden, out_o, P, H, S);
}

// round 16
// speedup vs baseline: 1.7565x; 1.0425x over previous
#include <cuda_runtime.h>
#include <cuda_fp16.h>
#include <cstdint>

// ===========================================================================
// InnerMonologue: FP16 GEMMs on mma.sync.m16n8k16, CTA 128x256, 16 warps
// (4x4) of 32x64, BK=64. GEMM1 fuses the fp32->fp16 A conversion (register
// prefetch + 2-buffer fp16 A smem); B always 3-stage cp.async. GEMM2 reads
// fp16 PR written by GEMM1's epilogue.
// Output: [PR (BS*P)] [OUT (BS*H)] [is_private (BS)] [usage (B)]  (all fp32)
// ===========================================================================

#define MAX_S 32768
#define MAX_WE (2048 * 256)
#define MAX_PR (32768 * 256)

__device__ unsigned char g_mask[MAX_S];
__device__ __half g_Wt16[MAX_WE];   // W_to  transposed [P][H] fp16
__device__ __half g_Wf16[MAX_WE];   // W_from transposed [H][P] fp16
__device__ __half g_PR16[MAX_PR];   // PR fp16 [BS][P] (written by GEMM1)

__device__ __forceinline__ uint32_t smem_u32(const void* p) {
    uint32_t a;
    asm("{ .reg .u64 t; cvta.to.shared.u64 t, %1; cvt.u32.u64 %0, t; }"
        : "=r"(a) : "l"(p));
    return a;
}
__device__ __forceinline__ void ldsm_x4(uint32_t addr, uint32_t* r) {
    asm volatile("ldmatrix.sync.aligned.m8n8.x4.shared.b16 {%0,%1,%2,%3}, [%4];"
                 : "=r"(r[0]), "=r"(r[1]), "=r"(r[2]), "=r"(r[3])
                 : "r"(addr));
}
__device__ __forceinline__ void mma_f16(float* c, const uint32_t* a,
                                        const uint32_t* b) {
    asm volatile(
        "mma.sync.aligned.m16n8k16.row.col.f32.f16.f16.f32 "
        "{%0,%1,%2,%3}, {%4,%5,%6,%7}, {%8,%9}, {%0,%1,%2,%3};"
        : "+f"(c[0]), "+f"(c[1]), "+f"(c[2]), "+f"(c[3])
        : "r"(a[0]), "r"(a[1]), "r"(a[2]), "r"(a[3]), "r"(b[0]), "r"(b[1]));
}
__device__ __forceinline__ void cp16(uint32_t dst, const void* src) {
    asm volatile("cp.async.cg.shared.global [%0], [%1], 16;"
                 :: "r"(dst), "l"(src));
}
#define CP_COMMIT() asm volatile("cp.async.commit_group;" ::: "memory")
#define CP_WAIT1()  asm volatile("cp.async.wait_group 1;" ::: "memory")

// SMEM rows: 64 fp16 (128B) + 16B pad = 144B stride -> conflict-free ldsm.
#define ROWB 144
#define A_T (128 * ROWB)               // 18432
#define B_T (256 * ROWB)               // 36864
// GEMM1 (fused A convert): [B stage x3][A buf x2] = 110592 + 36864 = 147456
// GEMM2 (cp.async A):      [A|B stage x3]         = 165888
#define SM_G1 (3 * B_T + 2 * A_T)
#define SM_G2 (3 * (A_T + B_T))

// ===========================================================================
// GEMM: C[128,256] = A[M,K]fp16 @ B[N,K]fp16^T + bias (+blend / +fp16 out).
// 512 threads, 16 warps (4M x 4N), warp tile 32x64, BK=64.
// A_FP32: A streamed fp32->regs->fp16 smem (2 buf); else 3-stage cp.async.
// ===========================================================================
template <bool MASKED, bool USE_WF, bool A_FP32, bool WRITE_F16>
__global__ void __launch_bounds__(512, 1)
gemm_f16(const float* __restrict__ A32, const float* __restrict__ bias,
         const float* __restrict__ HS, float* __restrict__ OUT,
         int K, int Ntot, int S) {
    extern __shared__ __align__(16) char smem[];
    __shared__ unsigned char smask[128];
    __shared__ int s_cnt;

    const __half* __restrict__ Ah = g_PR16;  // fp16 A source (GEMM2)
    const __half* __restrict__ Bw = USE_WF ? g_Wf16 : g_Wt16;

    const int tid = threadIdx.x;
    const int wid = tid >> 5;
    const int lane = tid & 31;
    const int m0 = blockIdx.y * 128;
    const int n0 = blockIdx.x * 256;

    if (MASKED) {
        if (tid == 0) s_cnt = 0;
        __syncthreads();
        if (tid < 128) {
            unsigned char mm = g_mask[(m0 + tid) % S];
            smask[tid] = mm;
            if (mm) atomicAdd(&s_cnt, 1);
        }
        __syncthreads();
        if (s_cnt == 0) {  // all-public tile: straight copy of HS slab
            const size_t base = (size_t)m0 * Ntot + n0;
            for (int i = tid; i < 128 * 64; i += 512) {
                int r = i >> 6, c = (i & 63) << 2;
                *(float4*)&OUT[base + (size_t)r * Ntot + c] =
                    *(const float4*)&HS[base + (size_t)r * Ntot + c];
            }
            return;
        }
    }

    const uint32_t sbase = smem_u32(smem);
    const int wm = (wid >> 2) * 32;   // 4 warp rows
    const int wn = (wid & 3) * 64;    // 4 warp cols (64 wide)

    // ---- B staging: 3-stage cp.async (2048 16B units, 4/thread) ----
    auto cp_B = [&](int s, int st) {
        const int k0 = s << 6;
        const uint32_t dB = sbase + (A_FP32 ? st * B_T : st * (A_T + B_T) + A_T);
#pragma unroll
        for (int i = 0; i < 4; i++) {
            int u = tid * 4 + i;
            int row = u >> 3, col = u & 7;
            cp16(dB + row * ROWB + col * 16,
                 Bw + (size_t)(n0 + row) * K + k0 + col * 8);
        }
    };
    // ---- A staging, fp16 path (GEMM2): 1024 units, 2/thread ----
    auto cp_A = [&](int s, int st) {
        const int k0 = s << 6;
        const uint32_t dA = sbase + st * (A_T + B_T);
#pragma unroll
        for (int i = 0; i < 2; i++) {
            int u = tid * 2 + i;
            int row = u >> 3, col = u & 7;
            cp16(dA + row * ROWB + col * 16,
                 Ah + (size_t)(m0 + row) * K + k0 + col * 8);
        }
    };
    // ---- A staging, fp32 fused path (GEMM1) ----
    const int arow = tid >> 2;          // 0..127
    const int acol = (tid & 3) * 16;    // 0,16,32,48 (fp32 elems)
    float areg[16];
    auto load_A_regs = [&](int s) {
        const float* ap = A32 + (size_t)(m0 + arow) * K + (s << 6) + acol;
#pragma unroll
        for (int i = 0; i < 4; i++)
            *(float4*)&areg[i * 4] = *(const float4*)(ap + i * 4);
    };
    auto store_A = [&](int buf) {
        __half2 h[8];
#pragma unroll
        for (int j = 0; j < 8; j++)
            h[j] = __floats2half2_rn(areg[2 * j], areg[2 * j + 1]);
        char* dst = smem + 3 * B_T + buf * A_T + arow * ROWB + acol * 2;
        *(uint4*)dst = *(uint4*)&h[0];
        *(uint4*)(dst + 16) = *(uint4*)&h[4];
    };

    float acc[2][8][4];
#pragma unroll
    for (int mt = 0; mt < 2; mt++)
#pragma unroll
        for (int nt = 0; nt < 8; nt++)
#pragma unroll
            for (int i = 0; i < 4; i++) acc[mt][nt][i] = 0.f;

    const int r8 = lane & 7;
    const int mat = lane >> 3;  // 0..3
    const uint32_t aoff0 = (uint32_t)((wm + (mat & 1) * 8 + r8) * ROWB +
                                      (mat >> 1) * 16);
    const uint32_t boff0 = (uint32_t)((wn + (mat & 1) * 8 + r8) * ROWB +
                                      (mat >> 1) * 16);

    auto compute = [&](uint32_t uA, uint32_t uB) {
#pragma unroll
        for (int ks = 0; ks < 4; ks++) {  // four k16 steps per BK=64
            const int kb = ks * 32;
            uint32_t af[2][4], bf[4][4];
#pragma unroll
            for (int mt = 0; mt < 2; mt++)
                ldsm_x4(uA + aoff0 + mt * 16 * ROWB + kb, af[mt]);
#pragma unroll
            for (int g = 0; g < 4; g++)
                ldsm_x4(uB + boff0 + g * 16 * ROWB + kb, bf[g]);
#pragma unroll
            for (int g = 0; g < 4; g++) {
                uint32_t b0[2] = {bf[g][0], bf[g][2]};
                uint32_t b1[2] = {bf[g][1], bf[g][3]};
#pragma unroll
                for (int mt = 0; mt < 2; mt++) {
                    mma_f16(acc[mt][2 * g], af[mt], b0);
                    mma_f16(acc[mt][2 * g + 1], af[mt], b1);
                }
            }
        }
    };

    const int nk = K >> 6;
    if (A_FP32) {
        load_A_regs(0);
        cp_B(0, 0); CP_COMMIT();
        if (nk > 1) cp_B(1, 1); CP_COMMIT();
        for (int s = 0; s < nk; s++) {
            const int st = s % 3;
            store_A(s & 1);
            CP_WAIT1();
            __syncthreads();
            if (s + 1 < nk) load_A_regs(s + 1);
            if (s + 2 < nk) {
                int st2 = st + 2; if (st2 >= 3) st2 -= 3;
                cp_B(s + 2, st2);
            }
            CP_COMMIT();
            compute(sbase + 3 * B_T + (s & 1) * A_T, sbase + st * B_T);
        }
    } else {
        cp_A(0, 0); cp_B(0, 0); CP_COMMIT();
        if (nk > 1) { cp_A(1, 1); cp_B(1, 1); } CP_COMMIT();
        int st = 0;
        for (int s = 0; s < nk; s++) {
            CP_WAIT1();
            __syncthreads();
            if (s + 2 < nk) {
                int st2 = st + 2; if (st2 >= 3) st2 -= 3;
                cp_A(s + 2, st2); cp_B(s + 2, st2);
            }
            CP_COMMIT();
            const uint32_t uA = sbase + st * (A_T + B_T);
            compute(uA, uA + A_T);
            if (++st == 3) st = 0;
        }
    }

    // ---- Epilogue ----
    const int qr = lane >> 2;
    const int qc = (lane & 3) * 2;
#pragma unroll
    for (int mt = 0; mt < 2; mt++) {
        const int lr0 = wm + mt * 16 + qr;
        const int lr1 = lr0 + 8;
        const size_t rb0 = (size_t)(m0 + lr0) * Ntot;
        const size_t rb1 = (size_t)(m0 + lr1) * Ntot;
        const bool p0 = !MASKED || (smask[lr0] != 0);
        const bool p1 = !MASKED || (smask[lr1] != 0);
#pragma unroll
        for (int nt = 0; nt < 8; nt++) {
            const int col = n0 + wn + nt * 8 + qc;
            float2 b2 = *(const float2*)&bias[col];
            float2 v0, v1;
            v0.x = acc[mt][nt][0] + b2.x;
            v0.y = acc[mt][nt][1] + b2.y;
            v1.x = acc[mt][nt][2] + b2.x;
            v1.y = acc[mt][nt][3] + b2.y;
            if (WRITE_F16) {  // GEMM1: also emit fp16 PR for GEMM2's A
                *(__half2*)&g_PR16[rb0 + col] = __floats2half2_rn(v0.x, v0.y);
                *(__half2*)&g_PR16[rb1 + col] = __floats2half2_rn(v1.x, v1.y);
            }
            if (MASKED) {
                if (!p0) v0 = *(const float2*)&HS[rb0 + col];
                if (!p1) v1 = *(const float2*)&HS[rb1 + col];
            }
            *(float2*)&OUT[rb0 + col] = v0;
            *(float2*)&OUT[rb1 + col] = v1;
        }
    }
}

// ===========================================================================
// Mask scan, broadcast, weight transpose+fp16 kernels.
// ===========================================================================
__global__ void scan_kernel(const int* __restrict__ tok,
                            const int* __restrict__ ttid_p,
                            float* __restrict__ usage_out, int B, int S) {
    __shared__ int stok[8192];
    __shared__ int sc[256];
    const int ttid = *ttid_p;
    const int tid = threadIdx.x;
    const bool fits = (S <= 8192);
    if (fits)
        for (int i = tid; i < S; i += 256) stok[i] = tok[i];
    __syncthreads();
    const int* src = fits ? stok : tok;

    const int chunk = (S + 255) / 256;
    const int start = tid * chunk;
    const int end = min(start + chunk, S);
    int cnt = 0;
    for (int i = start; i < end; i++) cnt += (src[i] == ttid);
    sc[tid] = cnt;
    __syncthreads();
    for (int off = 1; off < 256; off <<= 1) {
        int v = (tid >= off) ? sc[tid - off] : 0;
        __syncthreads();
        sc[tid] += v;
        __syncthreads();
    }
    int run = sc[tid] - cnt;
    int ones = 0;
    for (int i = start; i < end; i++) {
        run += (src[i] == ttid);
        unsigned char m = (unsigned char)(run & 1);
        g_mask[i] = m;
        ones += m;
    }
    __syncthreads();
    sc[tid] = ones;
    __syncthreads();
    for (int off = 128; off > 0; off >>= 1) {
        if (tid < off) sc[tid] += sc[tid + off];
        __syncthreads();
    }
    if (tid < B) usage_out[tid] = (float)sc[0] / (float)S;
}

__global__ void bcast_kernel(float* __restrict__ out_mask, int BS, int S) {
    int i = blockIdx.x * blockDim.x + threadIdx.x;
    if (i < BS) out_mask[i] = (float)g_mask[i % S];
}

__global__ void conv_w_kernel(const float* __restrict__ W_to,
                              const float* __restrict__ W_from, int H, int P) {
    int idx = blockIdx.x * blockDim.x + threadIdx.x;
    if (idx >= H * P) return;
    {  // W_to [H][P] -> Wt [P][H] fp16
        int k = idx / P, n = idx - k * P;
        g_Wt16[n * H + k] = __float2half_rn(W_to[idx]);
    }
    {  // W_from [P][H] -> Wf [H][P] fp16
        int p = idx / H, hh = idx - p * H;
        g_Wf16[hh * P + p] = __float2half_rn(W_from[idx]);
    }
}

// ===========================================================================
extern "C" void kernel_launch(void* const* d_in, const int* in_sizes, int n_in,
                              void* d_out, int out_size) {
    const float* hidden = (const float*)d_in[0];
    const float* W_to   = (const float*)d_in[1];
    const float* b_to   = (const float*)d_in[2];
    const float* W_from = (const float*)d_in[3];
    const float* b_from = (const float*)d_in[4];
    const int*   token  = (const int*)d_in[5];
    const int*   ttid   = (const int*)d_in[6];

    const int P  = in_sizes[2];
    const int H  = in_sizes[4];
    const int BS = in_sizes[5];
    const int B  = out_size - BS * (P + H + 1);
    const int S  = BS / B;

    float* out = (float*)d_out;
    float* out_pr    = out;
    float* out_o     = out + (size_t)BS * P;
    float* out_mask  = out_o + (size_t)BS * H;
    float* out_usage = out_mask + BS;

    cudaFuncSetAttribute(gemm_f16<false, false, true, true>,
                         cudaFuncAttributeMaxDynamicSharedMemorySize, SM_G1);
    cudaFuncSetAttribute(gemm_f16<true, true, false, false>,
                         cudaFuncAttributeMaxDynamicSharedMemorySize, SM_G2);

    scan_kernel<<<1, 256>>>(token, ttid, out_usage, B, S);
    bcast_kernel<<<(BS + 255) / 256, 256>>>(out_mask, BS, S);
    conv_w_kernel<<<(H * P + 255) / 256, 256>>>(W_to, W_from, H, P);

    // GEMM1: PR = HS @ W_to + b_to   (M=BS, N=P=256 -> 1 n-block, K=H)
    // A = hidden fp32, converted in-kernel; also emits fp16 PR.
    gemm_f16<false, false, true, true>
        <<<dim3(P / 256, BS / 128), 512, SM_G1>>>(
            hidden, b_to, nullptr, out_pr, H, P, S);

    // GEMM2: OUT = blend(PR @ W_from + b_from, HS)  (M=BS, N=H, K=P)
    gemm_f16<true, true, false, false>
        <<<dim3(H / 256, BS / 128), 512, SM_G2>>>(
            nullptr, b_from, hidden, out_o, P, H, S);
}